// round 5
// baseline (speedup 1.0000x reference)
#include <cuda_runtime.h>
#include <cuda_bf16.h>
#include <cstdint>

// Problem dims
#define BQ    16
#define NNODE 2048
#define EDIM  8192
#define DIMIN 64
#define DH    32
#define MDIM  NNODE          // 2048  (GEMM M = n)
#define NDIM  (BQ*DH)        // 512   (GEMM N = b*32+h)
#define KDIM  EDIM           // 8192  (GEMM K = e)

// GEMM tiling: cg2 pair covers 256(M) x 512(N) via two N=256 MMAs; split-K=8
#define TMP   256            // M per cluster pair
#define NH    256            // N per MMA instruction (2 halves -> 512)
#define BK    64
#define KSPLIT 8
#define CHUNKS (KDIM/BK/KSPLIT)   // 16 chunks per CTA
#define STAGES 2
// stage layout (bytes): Ahi 16K | Alo 16K | Bhi 32K | Blo 32K
#define AH_OFF 0
#define AL_OFF 16384
#define BH_OFF 32768
#define BL_OFF 65536
#define STAGE_BYTES 98304
#define SMEM_STAGE0 1024
#define SMEM_DYN (SMEM_STAGE0 + STAGES*STAGE_BYTES)   // 197632

// tcgen05 is an arch-specific ("a") feature: only emit its PTX in the sm_103a pass.
#if defined(__CUDA_ARCH__) && (defined(__CUDA_ARCH_FEAT_SM103_ALL) || \
    (defined(__CUDA_ARCH_SPECIFIC__) && (__CUDA_ARCH_SPECIFIC__ == 1030)))
#define USE_TCGEN05 1
#else
#define USE_TCGEN05 0
#endif

// ---------------- scratch (device globals; no allocations allowed) ----------
__device__ __align__(256) __nv_bfloat16 g_Xhi[(size_t)NDIM*KDIM];  // [c][e]
__device__ __align__(256) __nv_bfloat16 g_Xlo[(size_t)NDIM*KDIM];

// ---------------- PTX helpers (arch-neutral) --------------------------------
static __device__ __forceinline__ uint32_t smem_u32(const void* p) {
    uint32_t a;
    asm("{ .reg .u64 t; cvta.to.shared.u64 t, %1; cvt.u32.u64 %0, t; }"
        : "=r"(a) : "l"(p));
    return a;
}

#define MBARRIER_INIT(addr, cnt) \
    asm volatile("mbarrier.init.shared.b64 [%0], %1;" :: "r"((uint32_t)(addr)), "r"((uint32_t)(cnt)) : "memory")

// cta-scope acquire wait (local data)
#define MBARRIER_WAIT_PARITY(mbar_smem_addr, phase_parity) do { \
    uint32_t _mbar = (uint32_t)(mbar_smem_addr); \
    uint32_t _parity = (uint32_t)(phase_parity); \
    uint32_t _done; \
    asm volatile( \
        "{\n\t" \
        ".reg .pred p;\n\t" \
        "mbarrier.try_wait.parity.acquire.cta.shared::cta.b64 p, [%1], %2;\n\t" \
        "selp.b32 %0, 1, 0, p;\n\t" \
        "}" \
        : "=r"(_done) : "r"(_mbar), "r"(_parity) : "memory"); \
    if (!_done) { \
        asm volatile( \
            "{\n\t" \
            ".reg .pred P1;\n\t" \
            "WAIT_LOOP_%=:\n\t" \
            "mbarrier.try_wait.parity.acquire.cta.shared::cta.b64 P1, [%0], %1, 0x989680;\n\t" \
            "@P1 bra.uni WAIT_DONE_%=;\n\t" \
            "bra.uni WAIT_LOOP_%=;\n\t" \
            "WAIT_DONE_%=:\n\t" \
            "}" \
            :: "r"(_mbar), "r"(_parity) : "memory"); \
    } \
} while (0)

#if USE_TCGEN05
// cluster-scope acquire wait (consumer observing peer-CTA relay arrive)
#define MBARRIER_WAIT_PARITY_CLU(mbar_smem_addr, phase_parity) do { \
    uint32_t _mbar = (uint32_t)(mbar_smem_addr); \
    uint32_t _parity = (uint32_t)(phase_parity); \
    uint32_t _done; \
    asm volatile( \
        "{\n\t" \
        ".reg .pred p;\n\t" \
        "mbarrier.try_wait.parity.acquire.cluster.shared::cta.b64 p, [%1], %2;\n\t" \
        "selp.b32 %0, 1, 0, p;\n\t" \
        "}" \
        : "=r"(_done) : "r"(_mbar), "r"(_parity) : "memory"); \
    if (!_done) { \
        asm volatile( \
            "{\n\t" \
            ".reg .pred P1;\n\t" \
            "WAIT_LOOP_%=:\n\t" \
            "mbarrier.try_wait.parity.acquire.cluster.shared::cta.b64 P1, [%0], %1, 0x989680;\n\t" \
            "@P1 bra.uni WAIT_DONE_%=;\n\t" \
            "bra.uni WAIT_LOOP_%=;\n\t" \
            "WAIT_DONE_%=:\n\t" \
            "}" \
            :: "r"(_mbar), "r"(_parity) : "memory"); \
    } \
} while (0)

#define MBARRIER_ARRIVE_CLUSTER(local_mbar_addr, target_rank) \
    asm volatile( \
        "{\n\t" \
        ".reg .b32 remAddr;\n\t" \
        "mapa.shared::cluster.u32 remAddr, %0, %1;\n\t" \
        "mbarrier.arrive.shared::cluster.b64 _, [remAddr];\n\t" \
        "}" \
        :: "r"((uint32_t)(local_mbar_addr)), "r"((uint32_t)(target_rank)) : "memory")

#define MBARRIER_ARRIVE_LOCAL(addr) \
    asm volatile("mbarrier.arrive.release.cta.shared::cta.b64 _, [%0];" :: "r"((uint32_t)(addr)) : "memory")

#define CLUSTER_SYNC() do { \
    asm volatile("barrier.cluster.arrive.aligned;" ::: "memory"); \
    asm volatile("barrier.cluster.wait.aligned;" ::: "memory"); \
} while (0)

#define TCGEN05_ALLOC_CG2(smem_result_addr, nCols) \
    asm volatile("tcgen05.alloc.cta_group::2.sync.aligned.shared::cta.b32 [%0], %1;" \
        :: "r"((uint32_t)(smem_result_addr)), "r"((uint32_t)(nCols)) : "memory")
#define TCGEN05_DEALLOC_CG2(tmem_addr, nCols) \
    asm volatile("tcgen05.dealloc.cta_group::2.sync.aligned.b32 %0, %1;" :: "r"(tmem_addr), "r"(nCols))
#define TCGEN05_RELINQUISH_CG2() \
    asm volatile("tcgen05.relinquish_alloc_permit.cta_group::2.sync.aligned;")
#define TCGEN05_COMMIT_MC_CG2(mbar_smem_addr, cta_mask) \
    asm volatile("tcgen05.commit.cta_group::2.mbarrier::arrive::one.shared::cluster.multicast::cluster.b64 [%0], %1;" \
        :: "r"((uint32_t)(mbar_smem_addr)), "h"((uint16_t)(cta_mask)) : "memory")
#define TCGEN05_WAIT_LD()  asm volatile("tcgen05.wait::ld.sync.aligned;" ::: "memory")
#define TCGEN05_FENCE_BEFORE() asm volatile("tcgen05.fence::before_thread_sync;" ::: "memory")
#define TCGEN05_FENCE_AFTER()  asm volatile("tcgen05.fence::after_thread_sync;" ::: "memory")
#define FENCE_PROXY_ASYNC_CTA() asm volatile("fence.proxy.async.shared::cta;" ::: "memory")

#define TCGEN05_LD_32X32B_X32(r, tmem_addr) \
    asm volatile( \
        "tcgen05.ld.sync.aligned.32x32b.x32.b32 " \
        "{%0, %1, %2, %3, %4, %5, %6, %7, " \
        " %8, %9, %10, %11, %12, %13, %14, %15, " \
        " %16, %17, %18, %19, %20, %21, %22, %23, " \
        " %24, %25, %26, %27, %28, %29, %30, %31}, [%32];" \
        : "=r"((r)[0]),  "=r"((r)[1]),  "=r"((r)[2]),  "=r"((r)[3]), \
          "=r"((r)[4]),  "=r"((r)[5]),  "=r"((r)[6]),  "=r"((r)[7]), \
          "=r"((r)[8]),  "=r"((r)[9]),  "=r"((r)[10]), "=r"((r)[11]), \
          "=r"((r)[12]), "=r"((r)[13]), "=r"((r)[14]), "=r"((r)[15]), \
          "=r"((r)[16]), "=r"((r)[17]), "=r"((r)[18]), "=r"((r)[19]), \
          "=r"((r)[20]), "=r"((r)[21]), "=r"((r)[22]), "=r"((r)[23]), \
          "=r"((r)[24]), "=r"((r)[25]), "=r"((r)[26]), "=r"((r)[27]), \
          "=r"((r)[28]), "=r"((r)[29]), "=r"((r)[30]), "=r"((r)[31]) \
        : "r"(tmem_addr))

// SW128 SMEM descriptor (K-major, version=1, SBO=64, LBO=1)
static constexpr uint64_t SMEM_DESC_BASE_SW128 =
    (uint64_t(2)  << 61) | (uint64_t(1) << 46) | (uint64_t(64) << 32) | (uint64_t(1) << 16);
#define MAKE_SMEM_DESC(base_addr) (SMEM_DESC_BASE_SW128 | ((uint64_t)((base_addr) >> 4) & 0x3FFF))

// cg2 bf16 SS MMA (fp32 accumulate), 8 disable-output-lane regs = 0
static __device__ __forceinline__ void mma_f16_ss_cg2(
    uint32_t d_tmem, uint64_t a_desc, uint64_t b_desc, uint32_t idesc, bool acc)
{
    uint32_t en = acc ? 1u : 0u;
    asm volatile(
        "{\n\t"
        ".reg .pred p;\n\t"
        "setp.ne.u32 p, %4, 0;\n\t"
        "tcgen05.mma.cta_group::2.kind::f16 [%0], %1, %2, %3, "
        "{%5, %5, %5, %5, %5, %5, %5, %5}, p;\n\t"
        "}"
        :: "r"(d_tmem), "l"(a_desc), "l"(b_desc), "r"(idesc), "r"(en), "r"(0u)
        : "memory");
}

#define CP_ASYNC16(saddr, gptr) \
    asm volatile("cp.async.cg.shared.global [%0], [%1], 16;" :: "r"(saddr), "l"(gptr))

#define RED_ADD_V4(gptr, a0, a1, a2, a3) \
    asm volatile("red.global.add.v4.f32 [%0], {%1, %2, %3, %4};" \
        :: "l"(gptr), "f"(a0), "f"(a1), "f"(a2), "f"(a3) : "memory")
#endif // USE_TCGEN05

// idesc: dtype=F32(1<<4), atype=BF16(1<<7), btype=BF16(1<<10), N/8<<17, M/16<<24 (M=256,N=256)
static constexpr uint32_t MMA_IDESC2 =
    0x490u | ((NH / 8) << 17) | ((TMP / 16) << 24);

static __device__ __forceinline__ uint32_t swz(uint32_t off) {
    return off ^ ((off >> 3) & 0x70);
}

// ---------------- kernel 0: zero the output (split-K accumulates) -----------
__global__ void __launch_bounds__(256) zero_out_kernel(float* __restrict__ out)
{
    size_t i = (size_t)blockIdx.x * blockDim.x + threadIdx.x;
    reinterpret_cast<float4*>(out)[i] = make_float4(0.f, 0.f, 0.f, 0.f);
}

// ---------------- kernel 2: xe = relu(in @ W + bias), transposed + split -----
__global__ void __launch_bounds__(1024) xe_kernel(
    const float* __restrict__ in, const float* __restrict__ W, const float* __restrict__ bx)
{
    __shared__ float Ws[DIMIN][DH];        // [64][32]
    __shared__ float ins[32][DIMIN];       // [32][64]
    __shared__ uint32_t tr[32][33];        // [h][e_local], padded

    int tx = threadIdx.x, ty = threadIdx.y;
    int e0 = blockIdx.x * 32;
    int b  = blockIdx.y;
    int flat = ty * 32 + tx;

    reinterpret_cast<float*>(Ws)[flat]        = W[flat];
    reinterpret_cast<float*>(Ws)[flat + 1024] = W[flat + 1024];
    size_t row = ((size_t)b * EDIM + e0 + ty) * DIMIN;
    ins[ty][tx]      = in[row + tx];
    ins[ty][tx + 32] = in[row + tx + 32];
    __syncthreads();

    float acc = bx[tx];
#pragma unroll
    for (int d = 0; d < DIMIN; d++)
        acc = fmaf(ins[ty][d], Ws[d][tx], acc);
    acc = fmaxf(acc, 0.0f);

    __nv_bfloat16 h = __float2bfloat16(acc);
    __nv_bfloat16 l = __float2bfloat16(acc - __bfloat162float(h));
    tr[tx][ty] = (uint32_t)__bfloat16_as_ushort(h) | ((uint32_t)__bfloat16_as_ushort(l) << 16);
    __syncthreads();

    uint32_t v = tr[ty][tx];                // h = ty, e_local = tx
    size_t off = (size_t)(b * 32 + ty) * KDIM + e0 + tx;
    g_Xhi[off] = __ushort_as_bfloat16((unsigned short)(v & 0xffffu));
    g_Xlo[off] = __ushort_as_bfloat16((unsigned short)(v >> 16));
}

// ---------------- kernel 3: fused GEMM ---------------------------------------
// out[b,n,h] += sum_e (w*inci+b)[n,e] * X[c=b*32+h, e]
// Producers read w/inci/b fp32, convert to bf16 hi/lo in-register, STS to stage.
__global__ void __launch_bounds__(160, 1) __cluster_dims__(2, 1, 1)
gemm_kernel(float* __restrict__ out,
            const float* __restrict__ w, const float* __restrict__ inci,
            const float* __restrict__ bmat)
{
    extern __shared__ char smem[];
    const int tid = threadIdx.x;

#if USE_TCGEN05
    uint32_t rank;
    asm("mov.u32 %0, %%cluster_ctarank;" : "=r"(rank));
    const int pm = blockIdx.x >> 1;            // pair id: m0 = pm*256
    const int m0 = pm * TMP;
    const int kbase = blockIdx.z * CHUNKS * BK;

    uint32_t sb = smem_u32(smem);
    // layout: tmemptr@0, full[s]@16+8s, empty[s]@48+8s, done@80
    if (tid == 0) {
#pragma unroll
        for (int s = 0; s < STAGES; s++) {
            // 128 cp.async noinc arrivals + 128 explicit STS arrivals (+1 relay on rank0)
            MBARRIER_INIT(sb + 16 + 8 * s, (rank == 0) ? 257u : 256u);
            MBARRIER_INIT(sb + 48 + 8 * s, 1);
        }
        MBARRIER_INIT(sb + 80, 1);
    }
    __syncthreads();
    CLUSTER_SYNC();                            // barriers visible cluster-wide

    if ((tid >> 5) == 0) TCGEN05_ALLOC_CG2(sb + 0, 512);
    __syncthreads();
    uint32_t tmem;
    asm volatile("ld.shared.b32 %0, [%1];" : "=r"(tmem) : "r"(sb + 0));

    if (tid < 128) {
        // ---- producers ----
        const int arow = m0 + (int)rank * 128 + tid;
        const float* wp = w    + (size_t)arow * KDIM;
        const float* ip = inci + (size_t)arow * KDIM;
        const float* bp = bmat + (size_t)arow * KDIM;
        // B (X) rows this CTA supplies: half0 c = rank*128+tid, half1 c = 256+rank*128+tid
        const __nv_bfloat16* xh0 = g_Xhi + (size_t)((int)rank * 128 + tid) * KDIM;
        const __nv_bfloat16* xl0 = g_Xlo + (size_t)((int)rank * 128 + tid) * KDIM;
        const __nv_bfloat16* xh1 = g_Xhi + (size_t)(256 + (int)rank * 128 + tid) * KDIM;
        const __nv_bfloat16* xl1 = g_Xlo + (size_t)(256 + (int)rank * 128 + tid) * KDIM;
        const uint32_t rb0 = (uint32_t)tid * 128;          // smem row off, half0
        const uint32_t rb1 = (uint32_t)(128 + tid) * 128;  // half1
        int s = 0, ph = 1;
        for (int ch = 0; ch < CHUNKS; ch++) {
            MBARRIER_WAIT_PARITY(sb + 48 + 8 * s, ph);
            uint32_t stb = sb + SMEM_STAGE0 + s * STAGE_BYTES;
            const int k0 = kbase + ch * BK;
            // -- B via cp.async (32 x 16B) --
#pragma unroll
            for (int g = 0; g < 8; g++) {
                uint32_t sw0 = swz(rb0 + g * 16), sw1 = swz(rb1 + g * 16);
                CP_ASYNC16(stb + BH_OFF + sw0, xh0 + k0 + g * 8);
                CP_ASYNC16(stb + BL_OFF + sw0, xl0 + k0 + g * 8);
                CP_ASYNC16(stb + BH_OFF + sw1, xh1 + k0 + g * 8);
                CP_ASYNC16(stb + BL_OFF + sw1, xl1 + k0 + g * 8);
            }
            asm volatile("cp.async.mbarrier.arrive.noinc.shared::cta.b64 [%0];"
                         :: "r"(sb + 16 + 8 * s) : "memory");
            // -- A: fp32 -> bf16 hi/lo, STS --
            const float4* w4 = reinterpret_cast<const float4*>(wp + k0);
            const float4* i4 = reinterpret_cast<const float4*>(ip + k0);
            const float4* b4 = reinterpret_cast<const float4*>(bp + k0);
            const uint32_t ra = (uint32_t)tid * 128;
#pragma unroll
            for (int t = 0; t < 4; t++) {      // 16 k-values per t
                float av[16];
#pragma unroll
                for (int u = 0; u < 4; u++) {
                    float4 wv = w4[t * 4 + u], iv = i4[t * 4 + u], bv = b4[t * 4 + u];
                    av[u * 4 + 0] = fmaf(wv.x, iv.x, bv.x);
                    av[u * 4 + 1] = fmaf(wv.y, iv.y, bv.y);
                    av[u * 4 + 2] = fmaf(wv.z, iv.z, bv.z);
                    av[u * 4 + 3] = fmaf(wv.w, iv.w, bv.w);
                }
                uint32_t hw[8], lw[8];
#pragma unroll
                for (int u = 0; u < 8; u++) {
                    float a0 = av[2 * u], a1 = av[2 * u + 1];
                    __nv_bfloat16 h0 = __float2bfloat16(a0), h1 = __float2bfloat16(a1);
                    __nv_bfloat16 l0 = __float2bfloat16(a0 - __bfloat162float(h0));
                    __nv_bfloat16 l1 = __float2bfloat16(a1 - __bfloat162float(h1));
                    hw[u] = (uint32_t)__bfloat16_as_ushort(h0) | ((uint32_t)__bfloat16_as_ushort(h1) << 16);
                    lw[u] = (uint32_t)__bfloat16_as_ushort(l0) | ((uint32_t)__bfloat16_as_ushort(l1) << 16);
                }
                uint32_t s0 = swz(ra + (t * 2 + 0) * 16), s1 = swz(ra + (t * 2 + 1) * 16);
                asm volatile("st.shared.v4.b32 [%0], {%1,%2,%3,%4};"
                             :: "r"(stb + AH_OFF + s0), "r"(hw[0]), "r"(hw[1]), "r"(hw[2]), "r"(hw[3]) : "memory");
                asm volatile("st.shared.v4.b32 [%0], {%1,%2,%3,%4};"
                             :: "r"(stb + AH_OFF + s1), "r"(hw[4]), "r"(hw[5]), "r"(hw[6]), "r"(hw[7]) : "memory");
                asm volatile("st.shared.v4.b32 [%0], {%1,%2,%3,%4};"
                             :: "r"(stb + AL_OFF + s0), "r"(lw[0]), "r"(lw[1]), "r"(lw[2]), "r"(lw[3]) : "memory");
                asm volatile("st.shared.v4.b32 [%0], {%1,%2,%3,%4};"
                             :: "r"(stb + AL_OFF + s1), "r"(lw[4]), "r"(lw[5]), "r"(lw[6]), "r"(lw[7]) : "memory");
            }
            FENCE_PROXY_ASYNC_CTA();           // order generic STS before async-proxy MMA reads
            MBARRIER_ARRIVE_LOCAL(sb + 16 + 8 * s);
            if (++s == STAGES) { s = 0; ph ^= 1; }
        }
    } else if (tid == 128) {
        if (rank == 0) {
            // ---- consumer: single-thread cg2 MMA issuer ----
            int s = 0, ph = 0;
            for (int ch = 0; ch < CHUNKS; ch++) {
                MBARRIER_WAIT_PARITY_CLU(sb + 16 + 8 * s, ph);  // 256 local + 1 relay
                uint32_t stb = sb + SMEM_STAGE0 + s * STAGE_BYTES;
                uint64_t dAh = MAKE_SMEM_DESC(stb + AH_OFF);
                uint64_t dAl = MAKE_SMEM_DESC(stb + AL_OFF);
#pragma unroll
                for (int half = 0; half < 2; half++) {
                    uint64_t dBh = MAKE_SMEM_DESC(stb + BH_OFF + half * 16384);
                    uint64_t dBl = MAKE_SMEM_DESC(stb + BL_OFF + half * 16384);
                    uint32_t dD = tmem + half * NH;
#pragma unroll
                    for (int k = 0; k < 4; k++) {   // 4 x K16 per 64-K chunk
                        bool acc0 = !(ch == 0 && k == 0);
                        mma_f16_ss_cg2(dD, dAh + k * 2, dBh + k * 2, MMA_IDESC2, acc0);
                        mma_f16_ss_cg2(dD, dAh + k * 2, dBl + k * 2, MMA_IDESC2, true);
                        mma_f16_ss_cg2(dD, dAl + k * 2, dBh + k * 2, MMA_IDESC2, true);
                    }
                }
                TCGEN05_COMMIT_MC_CG2(sb + 48 + 8 * s, 0x3);   // free stage in BOTH CTAs
                if (++s == STAGES) { s = 0; ph ^= 1; }
            }
            TCGEN05_COMMIT_MC_CG2(sb + 80, 0x3);               // done, both CTAs
        } else {
            // ---- relay (rank 1): local full -> arrive on rank0's full ----
            int s = 0, ph = 0;
            for (int ch = 0; ch < CHUNKS; ch++) {
                MBARRIER_WAIT_PARITY(sb + 16 + 8 * s, ph);
                MBARRIER_ARRIVE_CLUSTER(sb + 16 + 8 * s, 0);
                if (++s == STAGES) { s = 0; ph ^= 1; }
            }
        }
    }

    __syncthreads();
    MBARRIER_WAIT_PARITY(sb + 80, 0);
    TCGEN05_FENCE_AFTER();

    if (tid < 128) {
        // this CTA's 128 rows x 512 cols; col group p => batch b=p, h=j
        const int n = m0 + (int)rank * 128 + tid;
#pragma unroll
        for (int p = 0; p < 16; p++) {
            uint32_t r[32];
            TCGEN05_LD_32X32B_X32(r, tmem + p * 32);
            TCGEN05_WAIT_LD();
            float* o = out + (((size_t)p * NNODE + n) << 5);
#pragma unroll
            for (int q = 0; q < 8; q++)
                RED_ADD_V4(o + 4 * q,
                           __uint_as_float(r[4 * q]),     __uint_as_float(r[4 * q + 1]),
                           __uint_as_float(r[4 * q + 2]), __uint_as_float(r[4 * q + 3]));
        }
        TCGEN05_FENCE_BEFORE();
    }
    __syncthreads();
    if ((tid >> 5) == 0) {
        TCGEN05_RELINQUISH_CG2();
        TCGEN05_DEALLOC_CG2(tmem, 512);
    }
    CLUSTER_SYNC();                            // no CTA exits with peer ops in flight
#else
    // ---------------- SIMT fp32 fallback (non-'a' compilation pass only) -----
    const int m0f = blockIdx.x * 128;
    const int kbasef = blockIdx.z * CHUNKS * BK;
    if (tid >= 128) return;
    float* As = reinterpret_cast<float*>(smem);            // [128][65]
    float* Bs = As + 128 * 65;                             // [64][128]
    const int tx = tid & 7, ty = tid >> 3;

    for (int cc = 0; cc < 4; cc++) {           // 4 column blocks of 128
        const int c0f = cc * 128;
        float acc[8][16];
#pragma unroll
        for (int i = 0; i < 8; i++)
#pragma unroll
            for (int j = 0; j < 16; j++) acc[i][j] = 0.0f;

        for (int ch = 0; ch < CHUNKS; ch++) {
            int k0 = kbasef + ch * BK;
            {
                const float* wr = w    + (size_t)(m0f + tid) * KDIM + k0;
                const float* ir = inci + (size_t)(m0f + tid) * KDIM + k0;
                const float* br = bmat + (size_t)(m0f + tid) * KDIM + k0;
#pragma unroll
                for (int e = 0; e < BK; e++)
                    As[tid * 65 + e] = fmaf(wr[e], ir[e], br[e]);
            }
            {
                const __nv_bfloat16* xh = g_Xhi + (size_t)(c0f + tid) * KDIM + k0;
                const __nv_bfloat16* xl = g_Xlo + (size_t)(c0f + tid) * KDIM + k0;
#pragma unroll
                for (int e = 0; e < BK; e++)
                    Bs[e * 128 + tid] = __bfloat162float(xh[e]) + __bfloat162float(xl[e]);
            }
            asm volatile("bar.sync 1, 128;" ::: "memory");
#pragma unroll 4
            for (int k = 0; k < BK; k++) {
                float a[8], bvx[16];
#pragma unroll
                for (int i = 0; i < 8; i++) a[i] = As[(ty * 8 + i) * 65 + k];
#pragma unroll
                for (int j = 0; j < 16; j++) bvx[j] = Bs[k * 128 + tx * 16 + j];
#pragma unroll
                for (int i = 0; i < 8; i++)
#pragma unroll
                    for (int j = 0; j < 16; j++)
                        acc[i][j] = fmaf(a[i], bvx[j], acc[i][j]);
            }
            asm volatile("bar.sync 1, 128;" ::: "memory");
        }
#pragma unroll
        for (int i = 0; i < 8; i++) {
            int n = m0f + ty * 8 + i;
#pragma unroll
            for (int j = 0; j < 16; j++) {
                int c = c0f + tx * 16 + j;
                atomicAdd(&out[(((size_t)(c >> 5) * NNODE + n) << 5) + (c & 31)], acc[i][j]);
            }
        }
        asm volatile("bar.sync 1, 128;" ::: "memory");
    }
#endif
}

// ---------------- launch ----------------------------------------------------
extern "C" void kernel_launch(void* const* d_in, const int* in_sizes, int n_in,
                              void* d_out, int out_size)
{
    const float* inputs = (const float*)d_in[0];   // [16, 8192, 64]
    const float* W_xes  = (const float*)d_in[1];   // [64, 32]
    const float* b_xes  = (const float*)d_in[2];   // [32]
    const float* inci   = (const float*)d_in[3];   // [2048, 8192]
    const float* w      = (const float*)d_in[4];   // [2048, 8192]
    const float* b      = (const float*)d_in[5];   // [2048, 8192]
    float* out = (float*)d_out;                    // [16, 2048, 32]

    // 0) zero output (split-K accumulates with red.add)
    zero_out_kernel<<<(NNODE * NDIM / 4) / 256, 256>>>(out);
    // 1) xe = relu(inputs @ W + bias), transposed to [c][e], bf16 hi/lo
    {
        dim3 grid(EDIM / 32, BQ), blk(32, 32);
        xe_kernel<<<grid, blk>>>(inputs, W_xes, b_xes);
    }
    // 2) fused cg2 GEMM (A-split in-kernel), split-K=8: 64 pairs = 128 CTAs
    {
        cudaFuncSetAttribute(gemm_kernel, cudaFuncAttributeMaxDynamicSharedMemorySize, SMEM_DYN);
        dim3 grid(MDIM / TMP * 2, 1, KSPLIT);   // (16, 1, 8)
        gemm_kernel<<<grid, 160, SMEM_DYN>>>(out, w, inci, b);
    }
}

// round 6
// speedup vs baseline: 1.1477x; 1.1477x over previous
#include <cuda_runtime.h>
#include <cuda_bf16.h>
#include <cstdint>

// Problem dims
#define BQ    16
#define NNODE 2048
#define EDIM  8192
#define DIMIN 64
#define DH    32
#define MDIM  NNODE          // 2048  (GEMM M = n)
#define NDIM  (BQ*DH)        // 512   (GEMM N = b*32+h)
#define KDIM  EDIM           // 8192  (GEMM K = e)

// GEMM tiling: cg2 pair covers 256(M) x 512(N) via two N=256 MMAs; split-K=8
#define TMP   256            // M per cluster pair
#define NH    256            // N per MMA instruction (2 halves -> 512)
#define BK    64
#define KSPLIT 8
#define CHUNKS (KDIM/BK/KSPLIT)   // 16 chunks per CTA
#define STAGES 2
// stage layout (bytes): Ahi 16K | Alo 16K | Bhi 32K | Blo 32K
#define AH_OFF 0
#define AL_OFF 16384
#define BH_OFF 32768
#define BL_OFF 65536
#define STAGE_BYTES 98304
#define SMEM_STAGE0 1024
#define SMEM_DYN (SMEM_STAGE0 + STAGES*STAGE_BYTES)   // 197632

// tcgen05 is an arch-specific ("a") feature: only emit its PTX in the sm_103a pass.
#if defined(__CUDA_ARCH__) && (defined(__CUDA_ARCH_FEAT_SM103_ALL) || \
    (defined(__CUDA_ARCH_SPECIFIC__) && (__CUDA_ARCH_SPECIFIC__ == 1030)))
#define USE_TCGEN05 1
#else
#define USE_TCGEN05 0
#endif

// ---------------- scratch (device globals; no allocations allowed) ----------
__device__ __align__(256) __nv_bfloat16 g_Xhi[(size_t)NDIM*KDIM];  // [c][e]
__device__ __align__(256) __nv_bfloat16 g_Xlo[(size_t)NDIM*KDIM];

// ---------------- PTX helpers (arch-neutral) --------------------------------
static __device__ __forceinline__ uint32_t smem_u32(const void* p) {
    uint32_t a;
    asm("{ .reg .u64 t; cvta.to.shared.u64 t, %1; cvt.u32.u64 %0, t; }"
        : "=r"(a) : "l"(p));
    return a;
}

#define MBARRIER_INIT(addr, cnt) \
    asm volatile("mbarrier.init.shared.b64 [%0], %1;" :: "r"((uint32_t)(addr)), "r"((uint32_t)(cnt)) : "memory")

// cta-scope acquire wait (local data)
#define MBARRIER_WAIT_PARITY(mbar_smem_addr, phase_parity) do { \
    uint32_t _mbar = (uint32_t)(mbar_smem_addr); \
    uint32_t _parity = (uint32_t)(phase_parity); \
    uint32_t _done; \
    asm volatile( \
        "{\n\t" \
        ".reg .pred p;\n\t" \
        "mbarrier.try_wait.parity.acquire.cta.shared::cta.b64 p, [%1], %2;\n\t" \
        "selp.b32 %0, 1, 0, p;\n\t" \
        "}" \
        : "=r"(_done) : "r"(_mbar), "r"(_parity) : "memory"); \
    if (!_done) { \
        asm volatile( \
            "{\n\t" \
            ".reg .pred P1;\n\t" \
            "WAIT_LOOP_%=:\n\t" \
            "mbarrier.try_wait.parity.acquire.cta.shared::cta.b64 P1, [%0], %1, 0x989680;\n\t" \
            "@P1 bra.uni WAIT_DONE_%=;\n\t" \
            "bra.uni WAIT_LOOP_%=;\n\t" \
            "WAIT_DONE_%=:\n\t" \
            "}" \
            :: "r"(_mbar), "r"(_parity) : "memory"); \
    } \
} while (0)

#if USE_TCGEN05
// cluster-scope acquire wait (consumer observing peer-CTA relay arrive)
#define MBARRIER_WAIT_PARITY_CLU(mbar_smem_addr, phase_parity) do { \
    uint32_t _mbar = (uint32_t)(mbar_smem_addr); \
    uint32_t _parity = (uint32_t)(phase_parity); \
    uint32_t _done; \
    asm volatile( \
        "{\n\t" \
        ".reg .pred p;\n\t" \
        "mbarrier.try_wait.parity.acquire.cluster.shared::cta.b64 p, [%1], %2;\n\t" \
        "selp.b32 %0, 1, 0, p;\n\t" \
        "}" \
        : "=r"(_done) : "r"(_mbar), "r"(_parity) : "memory"); \
    if (!_done) { \
        asm volatile( \
            "{\n\t" \
            ".reg .pred P1;\n\t" \
            "WAIT_LOOP_%=:\n\t" \
            "mbarrier.try_wait.parity.acquire.cluster.shared::cta.b64 P1, [%0], %1, 0x989680;\n\t" \
            "@P1 bra.uni WAIT_DONE_%=;\n\t" \
            "bra.uni WAIT_LOOP_%=;\n\t" \
            "WAIT_DONE_%=:\n\t" \
            "}" \
            :: "r"(_mbar), "r"(_parity) : "memory"); \
    } \
} while (0)

#define MBARRIER_ARRIVE_CLUSTER(local_mbar_addr, target_rank) \
    asm volatile( \
        "{\n\t" \
        ".reg .b32 remAddr;\n\t" \
        "mapa.shared::cluster.u32 remAddr, %0, %1;\n\t" \
        "mbarrier.arrive.shared::cluster.b64 _, [remAddr];\n\t" \
        "}" \
        :: "r"((uint32_t)(local_mbar_addr)), "r"((uint32_t)(target_rank)) : "memory")

#define MBARRIER_ARRIVE_LOCAL(addr) \
    asm volatile("mbarrier.arrive.release.cta.shared::cta.b64 _, [%0];" :: "r"((uint32_t)(addr)) : "memory")

#define CLUSTER_SYNC() do { \
    asm volatile("barrier.cluster.arrive.aligned;" ::: "memory"); \
    asm volatile("barrier.cluster.wait.aligned;" ::: "memory"); \
} while (0)

#define TCGEN05_ALLOC_CG2(smem_result_addr, nCols) \
    asm volatile("tcgen05.alloc.cta_group::2.sync.aligned.shared::cta.b32 [%0], %1;" \
        :: "r"((uint32_t)(smem_result_addr)), "r"((uint32_t)(nCols)) : "memory")
#define TCGEN05_DEALLOC_CG2(tmem_addr, nCols) \
    asm volatile("tcgen05.dealloc.cta_group::2.sync.aligned.b32 %0, %1;" :: "r"(tmem_addr), "r"(nCols))
#define TCGEN05_RELINQUISH_CG2() \
    asm volatile("tcgen05.relinquish_alloc_permit.cta_group::2.sync.aligned;")
#define TCGEN05_COMMIT_MC_CG2(mbar_smem_addr, cta_mask) \
    asm volatile("tcgen05.commit.cta_group::2.mbarrier::arrive::one.shared::cluster.multicast::cluster.b64 [%0], %1;" \
        :: "r"((uint32_t)(mbar_smem_addr)), "h"((uint16_t)(cta_mask)) : "memory")
#define TCGEN05_WAIT_LD()  asm volatile("tcgen05.wait::ld.sync.aligned;" ::: "memory")
#define TCGEN05_FENCE_BEFORE() asm volatile("tcgen05.fence::before_thread_sync;" ::: "memory")
#define TCGEN05_FENCE_AFTER()  asm volatile("tcgen05.fence::after_thread_sync;" ::: "memory")
#define FENCE_PROXY_ASYNC_CTA() asm volatile("fence.proxy.async.shared::cta;" ::: "memory")

#define TCGEN05_LD_32X32B_X32(r, tmem_addr) \
    asm volatile( \
        "tcgen05.ld.sync.aligned.32x32b.x32.b32 " \
        "{%0, %1, %2, %3, %4, %5, %6, %7, " \
        " %8, %9, %10, %11, %12, %13, %14, %15, " \
        " %16, %17, %18, %19, %20, %21, %22, %23, " \
        " %24, %25, %26, %27, %28, %29, %30, %31}, [%32];" \
        : "=r"((r)[0]),  "=r"((r)[1]),  "=r"((r)[2]),  "=r"((r)[3]), \
          "=r"((r)[4]),  "=r"((r)[5]),  "=r"((r)[6]),  "=r"((r)[7]), \
          "=r"((r)[8]),  "=r"((r)[9]),  "=r"((r)[10]), "=r"((r)[11]), \
          "=r"((r)[12]), "=r"((r)[13]), "=r"((r)[14]), "=r"((r)[15]), \
          "=r"((r)[16]), "=r"((r)[17]), "=r"((r)[18]), "=r"((r)[19]), \
          "=r"((r)[20]), "=r"((r)[21]), "=r"((r)[22]), "=r"((r)[23]), \
          "=r"((r)[24]), "=r"((r)[25]), "=r"((r)[26]), "=r"((r)[27]), \
          "=r"((r)[28]), "=r"((r)[29]), "=r"((r)[30]), "=r"((r)[31]) \
        : "r"(tmem_addr))

// SW128 SMEM descriptor (K-major, version=1, SBO=64, LBO=1)
static constexpr uint64_t SMEM_DESC_BASE_SW128 =
    (uint64_t(2)  << 61) | (uint64_t(1) << 46) | (uint64_t(64) << 32) | (uint64_t(1) << 16);
#define MAKE_SMEM_DESC(base_addr) (SMEM_DESC_BASE_SW128 | ((uint64_t)((base_addr) >> 4) & 0x3FFF))

// cg2 bf16 SS MMA (fp32 accumulate), 8 disable-output-lane regs = 0
static __device__ __forceinline__ void mma_f16_ss_cg2(
    uint32_t d_tmem, uint64_t a_desc, uint64_t b_desc, uint32_t idesc, bool acc)
{
    uint32_t en = acc ? 1u : 0u;
    asm volatile(
        "{\n\t"
        ".reg .pred p;\n\t"
        "setp.ne.u32 p, %4, 0;\n\t"
        "tcgen05.mma.cta_group::2.kind::f16 [%0], %1, %2, %3, "
        "{%5, %5, %5, %5, %5, %5, %5, %5}, p;\n\t"
        "}"
        :: "r"(d_tmem), "l"(a_desc), "l"(b_desc), "r"(idesc), "r"(en), "r"(0u)
        : "memory");
}

#define CP_ASYNC16(saddr, gptr) \
    asm volatile("cp.async.cg.shared.global [%0], [%1], 16;" :: "r"(saddr), "l"(gptr))

#define RED_ADD_V4(gptr, a0, a1, a2, a3) \
    asm volatile("red.global.add.v4.f32 [%0], {%1, %2, %3, %4};" \
        :: "l"(gptr), "f"(a0), "f"(a1), "f"(a2), "f"(a3) : "memory")
#endif // USE_TCGEN05

// idesc: dtype=F32(1<<4), atype=BF16(1<<7), btype=BF16(1<<10), N/8<<17, M/16<<24 (M=256,N=256)
static constexpr uint32_t MMA_IDESC2 =
    0x490u | ((NH / 8) << 17) | ((TMP / 16) << 24);

static __device__ __forceinline__ uint32_t swz(uint32_t off) {
    return off ^ ((off >> 3) & 0x70);
}

// ---------------- kernel 0: zero the output (split-K accumulates) -----------
__global__ void __launch_bounds__(256) zero_out_kernel(float* __restrict__ out)
{
    size_t i = (size_t)blockIdx.x * blockDim.x + threadIdx.x;
    reinterpret_cast<float4*>(out)[i] = make_float4(0.f, 0.f, 0.f, 0.f);
}

// ---------------- kernel 2: xe = relu(in @ W + bias), transposed + split -----
__global__ void __launch_bounds__(1024) xe_kernel(
    const float* __restrict__ in, const float* __restrict__ W, const float* __restrict__ bx)
{
    __shared__ float Ws[DIMIN][DH];        // [64][32]
    __shared__ float ins[32][DIMIN];       // [32][64]
    __shared__ uint32_t tr[32][33];        // [h][e_local], padded

    int tx = threadIdx.x, ty = threadIdx.y;
    int e0 = blockIdx.x * 32;
    int b  = blockIdx.y;
    int flat = ty * 32 + tx;

    reinterpret_cast<float*>(Ws)[flat]        = W[flat];
    reinterpret_cast<float*>(Ws)[flat + 1024] = W[flat + 1024];
    size_t row = ((size_t)b * EDIM + e0 + ty) * DIMIN;
    ins[ty][tx]      = in[row + tx];
    ins[ty][tx + 32] = in[row + tx + 32];
    __syncthreads();

    float acc = bx[tx];
#pragma unroll
    for (int d = 0; d < DIMIN; d++)
        acc = fmaf(ins[ty][d], Ws[d][tx], acc);
    acc = fmaxf(acc, 0.0f);

    __nv_bfloat16 h = __float2bfloat16(acc);
    __nv_bfloat16 l = __float2bfloat16(acc - __bfloat162float(h));
    tr[tx][ty] = (uint32_t)__bfloat16_as_ushort(h) | ((uint32_t)__bfloat16_as_ushort(l) << 16);
    __syncthreads();

    uint32_t v = tr[ty][tx];                // h = ty, e_local = tx
    size_t off = (size_t)(b * 32 + ty) * KDIM + e0 + tx;
    g_Xhi[off] = __ushort_as_bfloat16((unsigned short)(v & 0xffffu));
    g_Xlo[off] = __ushort_as_bfloat16((unsigned short)(v >> 16));
}

// ---------------- kernel 3: fused GEMM ---------------------------------------
// out[b,n,h] += sum_e (w*inci+b)[n,e] * X[c=b*32+h, e]
// Producers read w/inci/b fp32 COALESCED (16 lanes per row), convert to bf16
// hi/lo in-register, STS to SW128 stage; X staged via coalesced cp.async.
__global__ void __launch_bounds__(160, 1) __cluster_dims__(2, 1, 1)
gemm_kernel(float* __restrict__ out,
            const float* __restrict__ w, const float* __restrict__ inci,
            const float* __restrict__ bmat)
{
    extern __shared__ char smem[];
    const int tid = threadIdx.x;

#if USE_TCGEN05
    uint32_t rank;
    asm("mov.u32 %0, %%cluster_ctarank;" : "=r"(rank));
    const int pm = blockIdx.x >> 1;            // pair id: m0 = pm*256
    const int m0 = pm * TMP;
    const int kbase = blockIdx.z * CHUNKS * BK;

    uint32_t sb = smem_u32(smem);
    // layout: tmemptr@0, full[s]@16+8s, empty[s]@48+8s, done@80
    if (tid == 0) {
#pragma unroll
        for (int s = 0; s < STAGES; s++) {
            // 128 cp.async noinc arrivals + 128 explicit STS arrivals (+1 relay on rank0)
            MBARRIER_INIT(sb + 16 + 8 * s, (rank == 0) ? 257u : 256u);
            MBARRIER_INIT(sb + 48 + 8 * s, 1);
        }
        MBARRIER_INIT(sb + 80, 1);
    }
    __syncthreads();
    CLUSTER_SYNC();                            // barriers visible cluster-wide

    if ((tid >> 5) == 0) TCGEN05_ALLOC_CG2(sb + 0, 512);
    __syncthreads();
    uint32_t tmem;
    asm volatile("ld.shared.b32 %0, [%1];" : "=r"(tmem) : "r"(sb + 0));

    if (tid < 128) {
        // ---- producers (coalesced) ----
        const size_t rowbase = (size_t)(m0 + (int)rank * 128);
        const int crank = (int)rank * 128;
        int s = 0, ph = 1;
        for (int ch = 0; ch < CHUNKS; ch++) {
            MBARRIER_WAIT_PARITY(sb + 48 + 8 * s, ph);
            uint32_t stb = sb + SMEM_STAGE0 + s * STAGE_BYTES;
            const int k0 = kbase + ch * BK;
            // -- B (X hi/lo) via cp.async: 256 rows x 128B, 8 lanes per row --
#pragma unroll
            for (int j = 0; j < 16; j++) {
                int idx = j * 128 + tid;
                int r = idx >> 3, g = idx & 7;
                int c = crank + r + (r & 128);          // half0: c=crank+r; half1: +128 more
                size_t goff = (size_t)c * KDIM + k0 + g * 8;
                uint32_t so = swz((uint32_t)(r * 128 + g * 16));
                CP_ASYNC16(stb + BH_OFF + so, g_Xhi + goff);
                CP_ASYNC16(stb + BL_OFF + so, g_Xlo + goff);
            }
            asm volatile("cp.async.mbarrier.arrive.noinc.shared::cta.b64 [%0];"
                         :: "r"(sb + 16 + 8 * s) : "memory");
            // -- A: fp32 w/inci/b coalesced (16 lanes per row), cvt, STS --
#pragma unroll
            for (int j = 0; j < 16; j++) {
                int idx = j * 128 + tid;
                int r = idx >> 4, g = idx & 15;
                size_t goff = (rowbase + r) * KDIM + k0 + g * 4;
                float4 wv = *reinterpret_cast<const float4*>(w    + goff);
                float4 iv = *reinterpret_cast<const float4*>(inci + goff);
                float4 bv = *reinterpret_cast<const float4*>(bmat + goff);
                float a0 = fmaf(wv.x, iv.x, bv.x);
                float a1 = fmaf(wv.y, iv.y, bv.y);
                float a2 = fmaf(wv.z, iv.z, bv.z);
                float a3 = fmaf(wv.w, iv.w, bv.w);
                __nv_bfloat16 h0 = __float2bfloat16(a0), h1 = __float2bfloat16(a1);
                __nv_bfloat16 h2 = __float2bfloat16(a2), h3 = __float2bfloat16(a3);
                __nv_bfloat16 l0 = __float2bfloat16(a0 - __bfloat162float(h0));
                __nv_bfloat16 l1 = __float2bfloat16(a1 - __bfloat162float(h1));
                __nv_bfloat16 l2 = __float2bfloat16(a2 - __bfloat162float(h2));
                __nv_bfloat16 l3 = __float2bfloat16(a3 - __bfloat162float(h3));
                uint32_t hw0 = (uint32_t)__bfloat16_as_ushort(h0) | ((uint32_t)__bfloat16_as_ushort(h1) << 16);
                uint32_t hw1 = (uint32_t)__bfloat16_as_ushort(h2) | ((uint32_t)__bfloat16_as_ushort(h3) << 16);
                uint32_t lw0 = (uint32_t)__bfloat16_as_ushort(l0) | ((uint32_t)__bfloat16_as_ushort(l1) << 16);
                uint32_t lw1 = (uint32_t)__bfloat16_as_ushort(l2) | ((uint32_t)__bfloat16_as_ushort(l3) << 16);
                uint32_t so = swz((uint32_t)(r * 128 + (g >> 1) * 16)) + (g & 1) * 8;
                asm volatile("st.shared.v2.b32 [%0], {%1,%2};"
                             :: "r"(stb + AH_OFF + so), "r"(hw0), "r"(hw1) : "memory");
                asm volatile("st.shared.v2.b32 [%0], {%1,%2};"
                             :: "r"(stb + AL_OFF + so), "r"(lw0), "r"(lw1) : "memory");
            }
            FENCE_PROXY_ASYNC_CTA();           // order generic STS before async-proxy MMA reads
            MBARRIER_ARRIVE_LOCAL(sb + 16 + 8 * s);
            if (++s == STAGES) { s = 0; ph ^= 1; }
        }
    } else if (tid == 128) {
        if (rank == 0) {
            // ---- consumer: single-thread cg2 MMA issuer ----
            int s = 0, ph = 0;
            for (int ch = 0; ch < CHUNKS; ch++) {
                MBARRIER_WAIT_PARITY_CLU(sb + 16 + 8 * s, ph);  // 256 local + 1 relay
                uint32_t stb = sb + SMEM_STAGE0 + s * STAGE_BYTES;
                uint64_t dAh = MAKE_SMEM_DESC(stb + AH_OFF);
                uint64_t dAl = MAKE_SMEM_DESC(stb + AL_OFF);
#pragma unroll
                for (int half = 0; half < 2; half++) {
                    uint64_t dBh = MAKE_SMEM_DESC(stb + BH_OFF + half * 16384);
                    uint64_t dBl = MAKE_SMEM_DESC(stb + BL_OFF + half * 16384);
                    uint32_t dD = tmem + half * NH;
#pragma unroll
                    for (int k = 0; k < 4; k++) {   // 4 x K16 per 64-K chunk
                        bool acc0 = !(ch == 0 && k == 0);
                        mma_f16_ss_cg2(dD, dAh + k * 2, dBh + k * 2, MMA_IDESC2, acc0);
                        mma_f16_ss_cg2(dD, dAh + k * 2, dBl + k * 2, MMA_IDESC2, true);
                        mma_f16_ss_cg2(dD, dAl + k * 2, dBh + k * 2, MMA_IDESC2, true);
                    }
                }
                TCGEN05_COMMIT_MC_CG2(sb + 48 + 8 * s, 0x3);   // free stage in BOTH CTAs
                if (++s == STAGES) { s = 0; ph ^= 1; }
            }
            TCGEN05_COMMIT_MC_CG2(sb + 80, 0x3);               // done, both CTAs
        } else {
            // ---- relay (rank 1): local full -> arrive on rank0's full ----
            int s = 0, ph = 0;
            for (int ch = 0; ch < CHUNKS; ch++) {
                MBARRIER_WAIT_PARITY(sb + 16 + 8 * s, ph);
                MBARRIER_ARRIVE_CLUSTER(sb + 16 + 8 * s, 0);
                if (++s == STAGES) { s = 0; ph ^= 1; }
            }
        }
    }

    __syncthreads();
    MBARRIER_WAIT_PARITY(sb + 80, 0);
    TCGEN05_FENCE_AFTER();

    if (tid < 128) {
        // this CTA's 128 rows x 512 cols; col group p => batch b=p, h=j
        const int n = m0 + (int)rank * 128 + tid;
#pragma unroll
        for (int p = 0; p < 16; p++) {
            uint32_t r[32];
            TCGEN05_LD_32X32B_X32(r, tmem + p * 32);
            TCGEN05_WAIT_LD();
            float* o = out + (((size_t)p * NNODE + n) << 5);
#pragma unroll
            for (int q = 0; q < 8; q++)
                RED_ADD_V4(o + 4 * q,
                           __uint_as_float(r[4 * q]),     __uint_as_float(r[4 * q + 1]),
                           __uint_as_float(r[4 * q + 2]), __uint_as_float(r[4 * q + 3]));
        }
        TCGEN05_FENCE_BEFORE();
    }
    __syncthreads();
    if ((tid >> 5) == 0) {
        TCGEN05_RELINQUISH_CG2();
        TCGEN05_DEALLOC_CG2(tmem, 512);
    }
    CLUSTER_SYNC();                            // no CTA exits with peer ops in flight
#else
    // ---------------- SIMT fp32 fallback (non-'a' compilation pass only) -----
    const int m0f = blockIdx.x * 128;
    const int kbasef = blockIdx.z * CHUNKS * BK;
    if (tid >= 128) return;
    float* As = reinterpret_cast<float*>(smem);            // [128][65]
    float* Bs = As + 128 * 65;                             // [64][128]
    const int tx = tid & 7, ty = tid >> 3;

    for (int cc = 0; cc < 4; cc++) {           // 4 column blocks of 128
        const int c0f = cc * 128;
        float acc[8][16];
#pragma unroll
        for (int i = 0; i < 8; i++)
#pragma unroll
            for (int j = 0; j < 16; j++) acc[i][j] = 0.0f;

        for (int ch = 0; ch < CHUNKS; ch++) {
            int k0 = kbasef + ch * BK;
            {
                const float* wr = w    + (size_t)(m0f + tid) * KDIM + k0;
                const float* ir = inci + (size_t)(m0f + tid) * KDIM + k0;
                const float* br = bmat + (size_t)(m0f + tid) * KDIM + k0;
#pragma unroll
                for (int e = 0; e < BK; e++)
                    As[tid * 65 + e] = fmaf(wr[e], ir[e], br[e]);
            }
            {
                const __nv_bfloat16* xh = g_Xhi + (size_t)(c0f + tid) * KDIM + k0;
                const __nv_bfloat16* xl = g_Xlo + (size_t)(c0f + tid) * KDIM + k0;
#pragma unroll
                for (int e = 0; e < BK; e++)
                    Bs[e * 128 + tid] = __bfloat162float(xh[e]) + __bfloat162float(xl[e]);
            }
            asm volatile("bar.sync 1, 128;" ::: "memory");
#pragma unroll 4
            for (int k = 0; k < BK; k++) {
                float a[8], bvx[16];
#pragma unroll
                for (int i = 0; i < 8; i++) a[i] = As[(ty * 8 + i) * 65 + k];
#pragma unroll
                for (int j = 0; j < 16; j++) bvx[j] = Bs[k * 128 + tx * 16 + j];
#pragma unroll
                for (int i = 0; i < 8; i++)
#pragma unroll
                    for (int j = 0; j < 16; j++)
                        acc[i][j] = fmaf(a[i], bvx[j], acc[i][j]);
            }
            asm volatile("bar.sync 1, 128;" ::: "memory");
        }
#pragma unroll
        for (int i = 0; i < 8; i++) {
            int n = m0f + ty * 8 + i;
#pragma unroll
            for (int j = 0; j < 16; j++) {
                int c = c0f + tx * 16 + j;
                atomicAdd(&out[(((size_t)(c >> 5) * NNODE + n) << 5) + (c & 31)], acc[i][j]);
            }
        }
        asm volatile("bar.sync 1, 128;" ::: "memory");
    }
#endif
}

// ---------------- launch ----------------------------------------------------
extern "C" void kernel_launch(void* const* d_in, const int* in_sizes, int n_in,
                              void* d_out, int out_size)
{
    const float* inputs = (const float*)d_in[0];   // [16, 8192, 64]
    const float* W_xes  = (const float*)d_in[1];   // [64, 32]
    const float* b_xes  = (const float*)d_in[2];   // [32]
    const float* inci   = (const float*)d_in[3];   // [2048, 8192]
    const float* w      = (const float*)d_in[4];   // [2048, 8192]
    const float* b      = (const float*)d_in[5];   // [2048, 8192]
    float* out = (float*)d_out;                    // [16, 2048, 32]

    // 0) zero output (split-K accumulates with red.add)
    zero_out_kernel<<<(NNODE * NDIM / 4) / 256, 256>>>(out);
    // 1) xe = relu(inputs @ W + bias), transposed to [c][e], bf16 hi/lo
    {
        dim3 grid(EDIM / 32, BQ), blk(32, 32);
        xe_kernel<<<grid, blk>>>(inputs, W_xes, b_xes);
    }
    // 2) fused cg2 GEMM (A-split in-kernel), split-K=8: 64 pairs = 128 CTAs
    {
        cudaFuncSetAttribute(gemm_kernel, cudaFuncAttributeMaxDynamicSharedMemorySize, SMEM_DYN);
        dim3 grid(MDIM / TMP * 2, 1, KSPLIT);   // (16, 1, 8)
        gemm_kernel<<<grid, 160, SMEM_DYN>>>(out, w, inci, b);
    }
}

// round 7
// speedup vs baseline: 1.3327x; 1.1611x over previous
#include <cuda_runtime.h>
#include <cuda_bf16.h>
#include <cstdint>

// Problem dims
#define BQ    16
#define NNODE 2048
#define EDIM  8192
#define DIMIN 64
#define DH    32
#define MDIM  NNODE          // 2048  (GEMM M = n)
#define NDIM  (BQ*DH)        // 512   (GEMM N = b*32+h)
#define KDIM  EDIM           // 8192  (GEMM K = e)

// GEMM tiling: cg2 pair covers 256(M) x 512(N) via two N=256 MMAs; split-K=8
#define TMP   256            // M per cluster pair
#define NH    256            // N per MMA instruction (2 halves -> 512)
#define BK    32             // K per chunk (SW64: 64B rows)
#define KSPLIT 8
#define CHUNKS (KDIM/BK/KSPLIT)   // 32 chunks per CTA
#define STAGES 4
// stage layout (bytes): Ahi 8K | Alo 8K | Bhi 16K | Blo 16K
#define AH_OFF 0
#define AL_OFF 8192
#define BH_OFF 16384
#define BL_OFF 32768
#define STAGE_BYTES 49152
#define SMEM_STAGE0 1024
#define SMEM_DYN (SMEM_STAGE0 + STAGES*STAGE_BYTES)   // 197632

// tcgen05 is an arch-specific ("a") feature: only emit its PTX in the sm_103a pass.
#if defined(__CUDA_ARCH__) && (defined(__CUDA_ARCH_FEAT_SM103_ALL) || \
    (defined(__CUDA_ARCH_SPECIFIC__) && (__CUDA_ARCH_SPECIFIC__ == 1030)))
#define USE_TCGEN05 1
#else
#define USE_TCGEN05 0
#endif

// ---------------- scratch (device globals; no allocations allowed) ----------
__device__ __align__(256) __nv_bfloat16 g_Xhi[(size_t)NDIM*KDIM];  // [c][e]
__device__ __align__(256) __nv_bfloat16 g_Xlo[(size_t)NDIM*KDIM];

// ---------------- PTX helpers (arch-neutral) --------------------------------
static __device__ __forceinline__ uint32_t smem_u32(const void* p) {
    uint32_t a;
    asm("{ .reg .u64 t; cvta.to.shared.u64 t, %1; cvt.u32.u64 %0, t; }"
        : "=r"(a) : "l"(p));
    return a;
}

#define MBARRIER_INIT(addr, cnt) \
    asm volatile("mbarrier.init.shared.b64 [%0], %1;" :: "r"((uint32_t)(addr)), "r"((uint32_t)(cnt)) : "memory")

// cta-scope acquire wait (local data)
#define MBARRIER_WAIT_PARITY(mbar_smem_addr, phase_parity) do { \
    uint32_t _mbar = (uint32_t)(mbar_smem_addr); \
    uint32_t _parity = (uint32_t)(phase_parity); \
    uint32_t _done; \
    asm volatile( \
        "{\n\t" \
        ".reg .pred p;\n\t" \
        "mbarrier.try_wait.parity.acquire.cta.shared::cta.b64 p, [%1], %2;\n\t" \
        "selp.b32 %0, 1, 0, p;\n\t" \
        "}" \
        : "=r"(_done) : "r"(_mbar), "r"(_parity) : "memory"); \
    if (!_done) { \
        asm volatile( \
            "{\n\t" \
            ".reg .pred P1;\n\t" \
            "WAIT_LOOP_%=:\n\t" \
            "mbarrier.try_wait.parity.acquire.cta.shared::cta.b64 P1, [%0], %1, 0x989680;\n\t" \
            "@P1 bra.uni WAIT_DONE_%=;\n\t" \
            "bra.uni WAIT_LOOP_%=;\n\t" \
            "WAIT_DONE_%=:\n\t" \
            "}" \
            :: "r"(_mbar), "r"(_parity) : "memory"); \
    } \
} while (0)

#if USE_TCGEN05
// cluster-scope acquire wait (consumer observing peer-CTA relay arrive)
#define MBARRIER_WAIT_PARITY_CLU(mbar_smem_addr, phase_parity) do { \
    uint32_t _mbar = (uint32_t)(mbar_smem_addr); \
    uint32_t _parity = (uint32_t)(phase_parity); \
    uint32_t _done; \
    asm volatile( \
        "{\n\t" \
        ".reg .pred p;\n\t" \
        "mbarrier.try_wait.parity.acquire.cluster.shared::cta.b64 p, [%1], %2;\n\t" \
        "selp.b32 %0, 1, 0, p;\n\t" \
        "}" \
        : "=r"(_done) : "r"(_mbar), "r"(_parity) : "memory"); \
    if (!_done) { \
        asm volatile( \
            "{\n\t" \
            ".reg .pred P1;\n\t" \
            "WAIT_LOOP_%=:\n\t" \
            "mbarrier.try_wait.parity.acquire.cluster.shared::cta.b64 P1, [%0], %1, 0x989680;\n\t" \
            "@P1 bra.uni WAIT_DONE_%=;\n\t" \
            "bra.uni WAIT_LOOP_%=;\n\t" \
            "WAIT_DONE_%=:\n\t" \
            "}" \
            :: "r"(_mbar), "r"(_parity) : "memory"); \
    } \
} while (0)

#define MBARRIER_ARRIVE_CLUSTER(local_mbar_addr, target_rank) \
    asm volatile( \
        "{\n\t" \
        ".reg .b32 remAddr;\n\t" \
        "mapa.shared::cluster.u32 remAddr, %0, %1;\n\t" \
        "mbarrier.arrive.shared::cluster.b64 _, [remAddr];\n\t" \
        "}" \
        :: "r"((uint32_t)(local_mbar_addr)), "r"((uint32_t)(target_rank)) : "memory")

#define MBARRIER_ARRIVE_LOCAL(addr) \
    asm volatile("mbarrier.arrive.release.cta.shared::cta.b64 _, [%0];" :: "r"((uint32_t)(addr)) : "memory")

#define CLUSTER_SYNC() do { \
    asm volatile("barrier.cluster.arrive.aligned;" ::: "memory"); \
    asm volatile("barrier.cluster.wait.aligned;" ::: "memory"); \
} while (0)

#define TCGEN05_ALLOC_CG2(smem_result_addr, nCols) \
    asm volatile("tcgen05.alloc.cta_group::2.sync.aligned.shared::cta.b32 [%0], %1;" \
        :: "r"((uint32_t)(smem_result_addr)), "r"((uint32_t)(nCols)) : "memory")
#define TCGEN05_DEALLOC_CG2(tmem_addr, nCols) \
    asm volatile("tcgen05.dealloc.cta_group::2.sync.aligned.b32 %0, %1;" :: "r"(tmem_addr), "r"(nCols))
#define TCGEN05_RELINQUISH_CG2() \
    asm volatile("tcgen05.relinquish_alloc_permit.cta_group::2.sync.aligned;")
#define TCGEN05_COMMIT_MC_CG2(mbar_smem_addr, cta_mask) \
    asm volatile("tcgen05.commit.cta_group::2.mbarrier::arrive::one.shared::cluster.multicast::cluster.b64 [%0], %1;" \
        :: "r"((uint32_t)(mbar_smem_addr)), "h"((uint16_t)(cta_mask)) : "memory")
#define TCGEN05_WAIT_LD()  asm volatile("tcgen05.wait::ld.sync.aligned;" ::: "memory")
#define TCGEN05_FENCE_BEFORE() asm volatile("tcgen05.fence::before_thread_sync;" ::: "memory")
#define TCGEN05_FENCE_AFTER()  asm volatile("tcgen05.fence::after_thread_sync;" ::: "memory")
#define FENCE_PROXY_ASYNC_CTA() asm volatile("fence.proxy.async.shared::cta;" ::: "memory")

#define TCGEN05_LD_32X32B_X32(r, tmem_addr) \
    asm volatile( \
        "tcgen05.ld.sync.aligned.32x32b.x32.b32 " \
        "{%0, %1, %2, %3, %4, %5, %6, %7, " \
        " %8, %9, %10, %11, %12, %13, %14, %15, " \
        " %16, %17, %18, %19, %20, %21, %22, %23, " \
        " %24, %25, %26, %27, %28, %29, %30, %31}, [%32];" \
        : "=r"((r)[0]),  "=r"((r)[1]),  "=r"((r)[2]),  "=r"((r)[3]), \
          "=r"((r)[4]),  "=r"((r)[5]),  "=r"((r)[6]),  "=r"((r)[7]), \
          "=r"((r)[8]),  "=r"((r)[9]),  "=r"((r)[10]), "=r"((r)[11]), \
          "=r"((r)[12]), "=r"((r)[13]), "=r"((r)[14]), "=r"((r)[15]), \
          "=r"((r)[16]), "=r"((r)[17]), "=r"((r)[18]), "=r"((r)[19]), \
          "=r"((r)[20]), "=r"((r)[21]), "=r"((r)[22]), "=r"((r)[23]), \
          "=r"((r)[24]), "=r"((r)[25]), "=r"((r)[26]), "=r"((r)[27]), \
          "=r"((r)[28]), "=r"((r)[29]), "=r"((r)[30]), "=r"((r)[31]) \
        : "r"(tmem_addr))

// SW64 SMEM descriptor (K-major, 64B rows): layout=4, version=1, SBO=32, LBO=1
static constexpr uint64_t SMEM_DESC_BASE_SW64 =
    (uint64_t(4)  << 61) | (uint64_t(1) << 46) | (uint64_t(32) << 32) | (uint64_t(1) << 16);
#define MAKE_SMEM_DESC64(base_addr) (SMEM_DESC_BASE_SW64 | ((uint64_t)((base_addr) >> 4) & 0x3FFF))

// cg2 bf16 SS MMA (fp32 accumulate), 8 disable-output-lane regs = 0
static __device__ __forceinline__ void mma_f16_ss_cg2(
    uint32_t d_tmem, uint64_t a_desc, uint64_t b_desc, uint32_t idesc, bool acc)
{
    uint32_t en = acc ? 1u : 0u;
    asm volatile(
        "{\n\t"
        ".reg .pred p;\n\t"
        "setp.ne.u32 p, %4, 0;\n\t"
        "tcgen05.mma.cta_group::2.kind::f16 [%0], %1, %2, %3, "
        "{%5, %5, %5, %5, %5, %5, %5, %5}, p;\n\t"
        "}"
        :: "r"(d_tmem), "l"(a_desc), "l"(b_desc), "r"(idesc), "r"(en), "r"(0u)
        : "memory");
}

#define CP_ASYNC16(saddr, gptr) \
    asm volatile("cp.async.cg.shared.global [%0], [%1], 16;" :: "r"(saddr), "l"(gptr))

#define RED_ADD_V4(gptr, a0, a1, a2, a3) \
    asm volatile("red.global.add.v4.f32 [%0], {%1, %2, %3, %4};" \
        :: "l"(gptr), "f"(a0), "f"(a1), "f"(a2), "f"(a3) : "memory")
#endif // USE_TCGEN05

// idesc: dtype=F32(1<<4), atype=BF16(1<<7), btype=BF16(1<<10), N/8<<17, M/16<<24 (M=256,N=256)
static constexpr uint32_t MMA_IDESC2 =
    0x490u | ((NH / 8) << 17) | ((TMP / 16) << 24);

static __device__ __forceinline__ uint32_t swz64(uint32_t off) {
    return off ^ ((off >> 3) & 0x30);
}

// ---------------- kernel 1: xe = relu(in @ W + bias) -> X hi/lo; zeros out ---
// grid (64, 16), block 256. Block covers (b, e0..e0+127). Warp w -> h in [4w,4w+4).
__global__ void __launch_bounds__(256) xe_kernel(
    const float* __restrict__ in, const float* __restrict__ W,
    const float* __restrict__ bx, float* __restrict__ out)
{
    __shared__ float ins[128][68];     // padded: 272B rows (16B-aligned, conflict-light)
    __shared__ float Wt[32][68];       // W transposed [h][d]
    __shared__ float bs[32];

    const int tid = threadIdx.x;
    const int e0 = blockIdx.x * 128;
    const int b  = blockIdx.y;

    // fold output zeroing in: 1024 blocks x 256 thr x 16B = 4MB exactly
    size_t zi = ((size_t)blockIdx.y * gridDim.x + blockIdx.x) * 256 + tid;
    reinterpret_cast<float4*>(out)[zi] = make_float4(0.f, 0.f, 0.f, 0.f);

    // stage W transposed (2048 floats) + bias
    for (int t = tid; t < 2048; t += 256) {
        int d = t >> 5, h = t & 31;
        Wt[h][d] = W[t];
    }
    if (tid < 32) bs[tid] = bx[tid];
    // stage inputs: 128 rows x 64 fp32, coalesced float4
    {
        const float4* gin = reinterpret_cast<const float4*>(in + ((size_t)b * EDIM + e0) * DIMIN);
        for (int t = tid; t < 2048; t += 256) {
            int r = t >> 4, c4 = t & 15;
            *reinterpret_cast<float4*>(&ins[r][c4 * 4]) = gin[t];
        }
    }
    __syncthreads();

    const int wid = tid >> 5, lane = tid & 31;
    const int h0 = wid * 4;
#pragma unroll
    for (int p = 0; p < 4; p++) {
        int row = p * 32 + lane;
        float a0 = bs[h0], a1 = bs[h0 + 1], a2 = bs[h0 + 2], a3 = bs[h0 + 3];
#pragma unroll
        for (int d4 = 0; d4 < 16; d4++) {
            float4 v  = *reinterpret_cast<const float4*>(&ins[row][d4 * 4]);
            float4 w0 = *reinterpret_cast<const float4*>(&Wt[h0][d4 * 4]);
            float4 w1 = *reinterpret_cast<const float4*>(&Wt[h0 + 1][d4 * 4]);
            float4 w2 = *reinterpret_cast<const float4*>(&Wt[h0 + 2][d4 * 4]);
            float4 w3 = *reinterpret_cast<const float4*>(&Wt[h0 + 3][d4 * 4]);
            a0 = fmaf(v.x, w0.x, fmaf(v.y, w0.y, fmaf(v.z, w0.z, fmaf(v.w, w0.w, a0))));
            a1 = fmaf(v.x, w1.x, fmaf(v.y, w1.y, fmaf(v.z, w1.z, fmaf(v.w, w1.w, a1))));
            a2 = fmaf(v.x, w2.x, fmaf(v.y, w2.y, fmaf(v.z, w2.z, fmaf(v.w, w2.w, a2))));
            a3 = fmaf(v.x, w3.x, fmaf(v.y, w3.y, fmaf(v.z, w3.z, fmaf(v.w, w3.w, a3))));
        }
        float av[4] = {fmaxf(a0, 0.f), fmaxf(a1, 0.f), fmaxf(a2, 0.f), fmaxf(a3, 0.f)};
#pragma unroll
        for (int i = 0; i < 4; i++) {
            __nv_bfloat16 h = __float2bfloat16(av[i]);
            __nv_bfloat16 l = __float2bfloat16(av[i] - __bfloat162float(h));
            size_t off = (size_t)(b * 32 + h0 + i) * KDIM + e0 + row;
            g_Xhi[off] = h;
            g_Xlo[off] = l;
        }
    }
}

// ---------------- kernel 2: fused GEMM ---------------------------------------
// out[b,n,h] += sum_e (w*inci+b)[n,e] * X[c=b*32+h, e]
__global__ void __launch_bounds__(160, 1) __cluster_dims__(2, 1, 1)
gemm_kernel(float* __restrict__ out,
            const float* __restrict__ w, const float* __restrict__ inci,
            const float* __restrict__ bmat)
{
    extern __shared__ char smem[];
    const int tid = threadIdx.x;

#if USE_TCGEN05
    uint32_t rank;
    asm("mov.u32 %0, %%cluster_ctarank;" : "=r"(rank));
    const int pm = blockIdx.x >> 1;            // pair id: m0 = pm*256
    const int m0 = pm * TMP;
    const int kbase = blockIdx.z * CHUNKS * BK;

    uint32_t sb = smem_u32(smem);
    // layout: tmemptr@0, full[s]@16+8s, empty[s]@48+8s, done@80
    if (tid == 0) {
#pragma unroll
        for (int s = 0; s < STAGES; s++) {
            // 128 cp.async noinc arrivals + 128 explicit STS arrivals (+1 relay on rank0)
            MBARRIER_INIT(sb + 16 + 8 * s, (rank == 0) ? 257u : 256u);
            MBARRIER_INIT(sb + 48 + 8 * s, 1);
        }
        MBARRIER_INIT(sb + 80, 1);
    }
    __syncthreads();
    CLUSTER_SYNC();                            // barriers visible cluster-wide

    if ((tid >> 5) == 0) TCGEN05_ALLOC_CG2(sb + 0, 512);
    __syncthreads();
    uint32_t tmem;
    asm volatile("ld.shared.b32 %0, [%1];" : "=r"(tmem) : "r"(sb + 0));

    if (tid < 128) {
        // ---- producers (coalesced; SW64 rows of 64B) ----
        const size_t rowbase = (size_t)(m0 + (int)rank * 128);
        const int crank = (int)rank * 128;
        int s = 0, ph = 1;
        for (int ch = 0; ch < CHUNKS; ch++) {
            MBARRIER_WAIT_PARITY(sb + 48 + 8 * s, ph);
            uint32_t stb = sb + SMEM_STAGE0 + s * STAGE_BYTES;
            const int k0 = kbase + ch * BK;
            // -- B (X hi/lo) via cp.async: 256 rows x 64B, 4 lanes per row --
#pragma unroll
            for (int j = 0; j < 8; j++) {
                int idx = j * 128 + tid;
                int r = idx >> 2, g = idx & 3;
                int c = crank + r + (r & 128);          // half0: c=crank+r; half1: +128 more
                size_t goff = (size_t)c * KDIM + k0 + g * 8;
                uint32_t so = swz64((uint32_t)(r * 64 + g * 16));
                CP_ASYNC16(stb + BH_OFF + so, g_Xhi + goff);
                CP_ASYNC16(stb + BL_OFF + so, g_Xlo + goff);
            }
            asm volatile("cp.async.mbarrier.arrive.noinc.shared::cta.b64 [%0];"
                         :: "r"(sb + 16 + 8 * s) : "memory");
            // -- A: fp32 w/inci/b coalesced (8 lanes per 32-float row), cvt, STS --
#pragma unroll
            for (int j = 0; j < 8; j++) {
                int idx = j * 128 + tid;
                int r = idx >> 3, g = idx & 7;
                size_t goff = (rowbase + r) * KDIM + k0 + g * 4;
                float4 wv = *reinterpret_cast<const float4*>(w    + goff);
                float4 iv = *reinterpret_cast<const float4*>(inci + goff);
                float4 bv = *reinterpret_cast<const float4*>(bmat + goff);
                float a0 = fmaf(wv.x, iv.x, bv.x);
                float a1 = fmaf(wv.y, iv.y, bv.y);
                float a2 = fmaf(wv.z, iv.z, bv.z);
                float a3 = fmaf(wv.w, iv.w, bv.w);
                __nv_bfloat16 h0 = __float2bfloat16(a0), h1 = __float2bfloat16(a1);
                __nv_bfloat16 h2 = __float2bfloat16(a2), h3 = __float2bfloat16(a3);
                __nv_bfloat16 l0 = __float2bfloat16(a0 - __bfloat162float(h0));
                __nv_bfloat16 l1 = __float2bfloat16(a1 - __bfloat162float(h1));
                __nv_bfloat16 l2 = __float2bfloat16(a2 - __bfloat162float(h2));
                __nv_bfloat16 l3 = __float2bfloat16(a3 - __bfloat162float(h3));
                uint32_t hw0 = (uint32_t)__bfloat16_as_ushort(h0) | ((uint32_t)__bfloat16_as_ushort(h1) << 16);
                uint32_t hw1 = (uint32_t)__bfloat16_as_ushort(h2) | ((uint32_t)__bfloat16_as_ushort(h3) << 16);
                uint32_t lw0 = (uint32_t)__bfloat16_as_ushort(l0) | ((uint32_t)__bfloat16_as_ushort(l1) << 16);
                uint32_t lw1 = (uint32_t)__bfloat16_as_ushort(l2) | ((uint32_t)__bfloat16_as_ushort(l3) << 16);
                uint32_t so = swz64((uint32_t)(r * 64 + (g >> 1) * 16)) + (g & 1) * 8;
                asm volatile("st.shared.v2.b32 [%0], {%1,%2};"
                             :: "r"(stb + AH_OFF + so), "r"(hw0), "r"(hw1) : "memory");
                asm volatile("st.shared.v2.b32 [%0], {%1,%2};"
                             :: "r"(stb + AL_OFF + so), "r"(lw0), "r"(lw1) : "memory");
            }
            FENCE_PROXY_ASYNC_CTA();           // order generic STS before async-proxy MMA reads
            MBARRIER_ARRIVE_LOCAL(sb + 16 + 8 * s);
            if (++s == STAGES) { s = 0; ph ^= 1; }
        }
    } else if (tid == 128) {
        if (rank == 0) {
            // ---- consumer: single-thread cg2 MMA issuer ----
            int s = 0, ph = 0;
            for (int ch = 0; ch < CHUNKS; ch++) {
                MBARRIER_WAIT_PARITY_CLU(sb + 16 + 8 * s, ph);  // 256 local + 1 relay
                uint32_t stb = sb + SMEM_STAGE0 + s * STAGE_BYTES;
                uint64_t dAh = MAKE_SMEM_DESC64(stb + AH_OFF);
                uint64_t dAl = MAKE_SMEM_DESC64(stb + AL_OFF);
#pragma unroll
                for (int half = 0; half < 2; half++) {
                    uint64_t dBh = MAKE_SMEM_DESC64(stb + BH_OFF + half * 8192);
                    uint64_t dBl = MAKE_SMEM_DESC64(stb + BL_OFF + half * 8192);
                    uint32_t dD = tmem + half * NH;
#pragma unroll
                    for (int k = 0; k < BK / 16; k++) {   // 2 x K16 per 32-K chunk
                        bool acc0 = !(ch == 0 && k == 0);
                        mma_f16_ss_cg2(dD, dAh + k * 2, dBh + k * 2, MMA_IDESC2, acc0);
                        mma_f16_ss_cg2(dD, dAh + k * 2, dBl + k * 2, MMA_IDESC2, true);
                        mma_f16_ss_cg2(dD, dAl + k * 2, dBh + k * 2, MMA_IDESC2, true);
                    }
                }
                TCGEN05_COMMIT_MC_CG2(sb + 48 + 8 * s, 0x3);   // free stage in BOTH CTAs
                if (++s == STAGES) { s = 0; ph ^= 1; }
            }
            TCGEN05_COMMIT_MC_CG2(sb + 80, 0x3);               // done, both CTAs
        } else {
            // ---- relay (rank 1): local full -> arrive on rank0's full ----
            int s = 0, ph = 0;
            for (int ch = 0; ch < CHUNKS; ch++) {
                MBARRIER_WAIT_PARITY(sb + 16 + 8 * s, ph);
                MBARRIER_ARRIVE_CLUSTER(sb + 16 + 8 * s, 0);
                if (++s == STAGES) { s = 0; ph ^= 1; }
            }
        }
    }

    __syncthreads();
    MBARRIER_WAIT_PARITY(sb + 80, 0);
    TCGEN05_FENCE_AFTER();

    if (tid < 128) {
        // this CTA's 128 rows x 512 cols; col group p => batch b=p, h=j
        const int n = m0 + (int)rank * 128 + tid;
#pragma unroll
        for (int p = 0; p < 16; p++) {
            uint32_t r[32];
            TCGEN05_LD_32X32B_X32(r, tmem + p * 32);
            TCGEN05_WAIT_LD();
            float* o = out + (((size_t)p * NNODE + n) << 5);
#pragma unroll
            for (int q = 0; q < 8; q++)
                RED_ADD_V4(o + 4 * q,
                           __uint_as_float(r[4 * q]),     __uint_as_float(r[4 * q + 1]),
                           __uint_as_float(r[4 * q + 2]), __uint_as_float(r[4 * q + 3]));
        }
        TCGEN05_FENCE_BEFORE();
    }
    __syncthreads();
    if ((tid >> 5) == 0) {
        TCGEN05_RELINQUISH_CG2();
        TCGEN05_DEALLOC_CG2(tmem, 512);
    }
    CLUSTER_SYNC();                            // no CTA exits with peer ops in flight
#else
    // ---------------- SIMT fp32 fallback (non-'a' compilation pass only) -----
    const int m0f = blockIdx.x * 128;
    const int kbasef = blockIdx.z * CHUNKS * BK;
    if (tid >= 128) return;
    float* As = reinterpret_cast<float*>(smem);            // [128][65]
    float* Bs = As + 128 * 65;                             // [BK][128]
    const int tx = tid & 7, ty = tid >> 3;

    for (int cc = 0; cc < 4; cc++) {           // 4 column blocks of 128
        const int c0f = cc * 128;
        float acc[8][16];
#pragma unroll
        for (int i = 0; i < 8; i++)
#pragma unroll
            for (int j = 0; j < 16; j++) acc[i][j] = 0.0f;

        for (int ch = 0; ch < CHUNKS; ch++) {
            int k0 = kbasef + ch * BK;
            {
                const float* wr = w    + (size_t)(m0f + tid) * KDIM + k0;
                const float* ir = inci + (size_t)(m0f + tid) * KDIM + k0;
                const float* br = bmat + (size_t)(m0f + tid) * KDIM + k0;
#pragma unroll
                for (int e = 0; e < BK; e++)
                    As[tid * 65 + e] = fmaf(wr[e], ir[e], br[e]);
            }
            {
                const __nv_bfloat16* xh = g_Xhi + (size_t)(c0f + tid) * KDIM + k0;
                const __nv_bfloat16* xl = g_Xlo + (size_t)(c0f + tid) * KDIM + k0;
#pragma unroll
                for (int e = 0; e < BK; e++)
                    Bs[e * 128 + tid] = __bfloat162float(xh[e]) + __bfloat162float(xl[e]);
            }
            asm volatile("bar.sync 1, 128;" ::: "memory");
#pragma unroll 4
            for (int k = 0; k < BK; k++) {
                float a[8], bvx[16];
#pragma unroll
                for (int i = 0; i < 8; i++) a[i] = As[(ty * 8 + i) * 65 + k];
#pragma unroll
                for (int j = 0; j < 16; j++) bvx[j] = Bs[k * 128 + tx * 16 + j];
#pragma unroll
                for (int i = 0; i < 8; i++)
#pragma unroll
                    for (int j = 0; j < 16; j++)
                        acc[i][j] = fmaf(a[i], bvx[j], acc[i][j]);
            }
            asm volatile("bar.sync 1, 128;" ::: "memory");
        }
#pragma unroll
        for (int i = 0; i < 8; i++) {
            int n = m0f + ty * 8 + i;
#pragma unroll
            for (int j = 0; j < 16; j++) {
                int c = c0f + tx * 16 + j;
                atomicAdd(&out[(((size_t)(c >> 5) * NNODE + n) << 5) + (c & 31)], acc[i][j]);
            }
        }
        asm volatile("bar.sync 1, 128;" ::: "memory");
    }
#endif
}

// ---------------- launch ----------------------------------------------------
extern "C" void kernel_launch(void* const* d_in, const int* in_sizes, int n_in,
                              void* d_out, int out_size)
{
    const float* inputs = (const float*)d_in[0];   // [16, 8192, 64]
    const float* W_xes  = (const float*)d_in[1];   // [64, 32]
    const float* b_xes  = (const float*)d_in[2];   // [32]
    const float* inci   = (const float*)d_in[3];   // [2048, 8192]
    const float* w      = (const float*)d_in[4];   // [2048, 8192]
    const float* b      = (const float*)d_in[5];   // [2048, 8192]
    float* out = (float*)d_out;                    // [16, 2048, 32]

    // 1) xe = relu(inputs @ W + bias) -> X hi/lo; also zeroes out (split-K accumulates)
    {
        dim3 grid(EDIM / 128, BQ);                 // (64, 16)
        xe_kernel<<<grid, 256>>>(inputs, W_xes, b_xes, out);
    }
    // 2) fused cg2 GEMM (A-split in-kernel), split-K=8: 64 pairs = 128 CTAs
    {
        cudaFuncSetAttribute(gemm_kernel, cudaFuncAttributeMaxDynamicSharedMemorySize, SMEM_DYN);
        dim3 grid(MDIM / TMP * 2, 1, KSPLIT);      // (16, 1, 8)
        gemm_kernel<<<grid, 160, SMEM_DYN>>>(out, w, inci, b);
    }
}